// round 3
// baseline (speedup 1.0000x reference)
#include <cuda_runtime.h>
#include <cuda_bf16.h>
#include <cstdint>

// Problem constants (fixed by the reference)
#define BB 32
#define LL 4096
#define HH 1024
#define GCH 4            // g-dimension split for the hid@W gemv
#define LPW 16           // encoder rows handled per warp in the energies kernel

// Scratch (allocation-free rule: __device__ globals)
__device__ float g_vpart[GCH * BB * HH];   // 512 KB
__device__ float g_v[BB * HH];             // 128 KB
__device__ float g_energy[BB * LL];        // 512 KB

// ---------------------------------------------------------------------------
// Kernel 1: partial v[b,h] = sum_{g in chunk} hid[b,g] * W[g,h]
// grid (HH/128, BB/4, GCH), 128 threads. Each thread: 1 h, 4 b, 256 g.
// W traffic = 32 MiB total, L2-resident after first touch.
// ---------------------------------------------------------------------------
__global__ void gemv_partial_kernel(const float* __restrict__ hid,
                                    const float* __restrict__ W) {
    const int h  = blockIdx.x * 128 + threadIdx.x;
    const int b0 = blockIdx.y * 4;
    const int g0 = blockIdx.z * (HH / GCH);   // 256-wide g chunk

    const float* Wp = W + (size_t)g0 * HH + h;
    const float* h0 = hid + (size_t)b0 * HH + g0;

    float a0 = 0.f, a1 = 0.f, a2 = 0.f, a3 = 0.f;
#pragma unroll 8
    for (int g = 0; g < HH / GCH; ++g) {
        const float w = Wp[(size_t)g * HH];
        a0 = fmaf(h0[g], w, a0);
        a1 = fmaf(h0[g + HH], w, a1);
        a2 = fmaf(h0[g + 2 * HH], w, a2);
        a3 = fmaf(h0[g + 3 * HH], w, a3);
    }
    float* vp = g_vpart + (size_t)blockIdx.z * BB * HH;
    vp[(b0 + 0) * HH + h] = a0;
    vp[(b0 + 1) * HH + h] = a1;
    vp[(b0 + 2) * HH + h] = a2;
    vp[(b0 + 3) * HH + h] = a3;
}

// ---------------------------------------------------------------------------
// Kernel 2: fold the GCH partials into g_v
// ---------------------------------------------------------------------------
__global__ void fold_v_kernel() {
    const int i = blockIdx.x * 256 + threadIdx.x;   // i < BB*HH
    float s = g_vpart[i];
#pragma unroll
    for (int c = 1; c < GCH; ++c) s += g_vpart[c * BB * HH + i];
    g_v[i] = s;
}

// ---------------------------------------------------------------------------
// Kernel 3: energies[b,l] = enc[l,b,:] . v[b,:]
// One warp per (b, LPW consecutive l rows). v[b] lives in 8 float4 registers
// per lane and is reused across LPW rows. grid (LL/(8*LPW), BB), 256 threads.
// This kernel streams all 512 MiB of enc -> it sets the runtime floor.
// ---------------------------------------------------------------------------
__global__ void energies_kernel(const float* __restrict__ enc) {
    const int warp = threadIdx.x >> 5;
    const int lane = threadIdx.x & 31;
    const int b    = blockIdx.y;
    const int l0   = (blockIdx.x * 8 + warp) * LPW;

    // Load v[b] into registers: 1024 floats / warp = 8 float4 per lane
    const float4* vp = reinterpret_cast<const float4*>(g_v + (size_t)b * HH);
    float4 v[8];
#pragma unroll
    for (int i = 0; i < 8; ++i) v[i] = vp[i * 32 + lane];

    // enc row pointer for (l0, b); rows advance by B*H floats per l
    const float4* ep = reinterpret_cast<const float4*>(enc) +
                       ((size_t)l0 * BB + b) * (HH / 4);
    const size_t row_stride = (size_t)BB * (HH / 4);

    for (int j = 0; j < LPW; ++j) {
        const float4* row = ep + (size_t)j * row_stride;
        float acc = 0.f;
#pragma unroll
        for (int i = 0; i < 8; ++i) {
            const float4 x = row[i * 32 + lane];
            acc = fmaf(x.x, v[i].x, acc);
            acc = fmaf(x.y, v[i].y, acc);
            acc = fmaf(x.z, v[i].z, acc);
            acc = fmaf(x.w, v[i].w, acc);
        }
#pragma unroll
        for (int o = 16; o; o >>= 1)
            acc += __shfl_xor_sync(0xffffffffu, acc, o);
        if (lane == 0) g_energy[(size_t)b * LL + l0 + j] = acc;
    }
}

// ---------------------------------------------------------------------------
// Kernel 4: row softmax over L=4096 per b; one block per b, 1024 threads.
// Writes final output [B,1,L].
// ---------------------------------------------------------------------------
__global__ void softmax_kernel(float* __restrict__ out) {
    const int b = blockIdx.x;
    const int t = threadIdx.x;
    __shared__ float sh[32];
    __shared__ float bcast;

    float e[4];
    float m = -1e30f;
#pragma unroll
    for (int i = 0; i < 4; ++i) {
        e[i] = g_energy[(size_t)b * LL + t + i * 1024];
        m = fmaxf(m, e[i]);
    }
#pragma unroll
    for (int o = 16; o; o >>= 1)
        m = fmaxf(m, __shfl_xor_sync(0xffffffffu, m, o));
    if ((t & 31) == 0) sh[t >> 5] = m;
    __syncthreads();
    if (t < 32) {
        float v = sh[t];
#pragma unroll
        for (int o = 16; o; o >>= 1)
            v = fmaxf(v, __shfl_xor_sync(0xffffffffu, v, o));
        if (t == 0) bcast = v;
    }
    __syncthreads();
    m = bcast;

    float s = 0.f;
#pragma unroll
    for (int i = 0; i < 4; ++i) {
        e[i] = expf(e[i] - m);
        s += e[i];
    }
#pragma unroll
    for (int o = 16; o; o >>= 1)
        s += __shfl_xor_sync(0xffffffffu, s, o);
    if ((t & 31) == 0) sh[t >> 5] = s;
    __syncthreads();
    if (t < 32) {
        float v = sh[t];
#pragma unroll
        for (int o = 16; o; o >>= 1)
            v += __shfl_xor_sync(0xffffffffu, v, o);
        if (t == 0) bcast = v;
    }
    __syncthreads();
    const float inv = 1.0f / bcast;
#pragma unroll
    for (int i = 0; i < 4; ++i)
        out[(size_t)b * LL + t + i * 1024] = e[i] * inv;
}

// ---------------------------------------------------------------------------
extern "C" void kernel_launch(void* const* d_in, const int* in_sizes, int n_in,
                              void* d_out, int out_size) {
    // Identify inputs by element count (all distinct): robust to ordering.
    const float* hid = nullptr;   // 32*1024      = 32768
    const float* enc = nullptr;   // 4096*32*1024 = 134217728
    const float* W   = nullptr;   // 1024*1024    = 1048576
    for (int i = 0; i < n_in; ++i) {
        const int s = in_sizes[i];
        if (s == BB * HH)            hid = (const float*)d_in[i];
        else if (s == HH * HH)       W   = (const float*)d_in[i];
        else if (s == 1024)          { /* bias: constant per-b shift, softmax-invariant (and zero) */ }
        else                         enc = (const float*)d_in[i];
    }
    float* out = (float*)d_out;

    gemv_partial_kernel<<<dim3(HH / 128, BB / 4, GCH), 128>>>(hid, W);
    fold_v_kernel<<<(BB * HH) / 256, 256>>>();
    energies_kernel<<<dim3(LL / (8 * LPW), BB), 256>>>(enc);
    softmax_kernel<<<BB, 1024>>>(out);
}

// round 6
// speedup vs baseline: 1.3181x; 1.3181x over previous
#include <cuda_runtime.h>
#include <cuda_bf16.h>
#include <cstdint>

// Problem constants (fixed by the reference)
#define BB 32
#define LL 4096
#define HH 1024
#define GCH 32           // g-dimension chunks for the hid@W gemv (32 g each)
#define LPW 16           // encoder rows handled per warp in the energies kernel
#define WPB 8            // warps per block in energies

// Scratch (allocation-free rule: __device__ globals)
__device__ float g_vpart[GCH * BB * HH];   // 4 MiB
__device__ float g_v[BB * HH];             // 128 KB
__device__ float g_energy[BB * LL];        // 512 KB

// ---------------------------------------------------------------------------
// Kernel 1: partial v[b,h] over a 32-wide g chunk, ALL 32 b batched per thread
// so W is read exactly once (4 MiB DRAM traffic total).
// grid (HH/128, GCH), 128 threads. Each thread: 1 h, 32 g, 32 b accumulators.
// ---------------------------------------------------------------------------
__global__ void gemv_partial_kernel(const float* __restrict__ hid,
                                    const float* __restrict__ W) {
    const int h  = blockIdx.x * 128 + threadIdx.x;
    const int g0 = blockIdx.y * (HH / GCH);   // 32-wide g chunk
    const int t  = threadIdx.x;

    // Stage hid[:, g0:g0+32] into smem: 32 b x 32 g = 1024 floats = 256 float4.
    // 128 threads -> two passes (R3 bug: single pass only covered b 0..15).
    __shared__ float hsh[BB][HH / GCH];
#pragma unroll
    for (int r = 0; r < 2; ++r) {
        const int b = r * 16 + (t >> 3);   // 8 threads per b-row, 4 floats each
        const int c = (t & 7) * 4;
        const float4 hv = *reinterpret_cast<const float4*>(hid + (size_t)b * HH + g0 + c);
        hsh[b][c + 0] = hv.x; hsh[b][c + 1] = hv.y;
        hsh[b][c + 2] = hv.z; hsh[b][c + 3] = hv.w;
    }
    __syncthreads();

    float acc[BB];
#pragma unroll
    for (int b = 0; b < BB; ++b) acc[b] = 0.f;

    const float* Wp = W + (size_t)g0 * HH + h;
#pragma unroll 8
    for (int g = 0; g < HH / GCH; ++g) {
        const float w = Wp[(size_t)g * HH];
#pragma unroll
        for (int b = 0; b < BB; ++b)
            acc[b] = fmaf(hsh[b][g], w, acc[b]);   // hsh read is warp-uniform broadcast
    }

    float* vp = g_vpart + (size_t)blockIdx.y * BB * HH;
#pragma unroll
    for (int b = 0; b < BB; ++b)
        vp[(size_t)b * HH + h] = acc[b];
}

// ---------------------------------------------------------------------------
// Kernel 2: fold the GCH partials into g_v (reads 4 MiB, writes 128 KB)
// ---------------------------------------------------------------------------
__global__ void fold_v_kernel() {
    const int i = blockIdx.x * 256 + threadIdx.x;   // i < BB*HH
    float s = 0.f;
#pragma unroll 8
    for (int c = 0; c < GCH; ++c) s += g_vpart[c * BB * HH + i];
    g_v[i] = s;
}

// ---------------------------------------------------------------------------
// Kernel 3: energies[b,l] = enc[l,b,:] . v[b,:]     (streams 512 MiB -> floor)
// v[b] staged in smem (4 KB) -> low regs -> 4 CTAs/SM -> 32 warps, 32KB in
// flight per SM. Deferred warp reduction: acc[16] reduced after the stream
// loop; lane 0 stores 4x STG.128.
// ---------------------------------------------------------------------------
__global__ void __launch_bounds__(32 * WPB) energies_kernel(const float* __restrict__ enc) {
    const int warp = threadIdx.x >> 5;
    const int lane = threadIdx.x & 31;
    const int b    = blockIdx.y;
    const int l0   = (blockIdx.x * WPB + warp) * LPW;

    __shared__ float4 vsh[HH / 4];   // 4 KB: v[b] as 256 float4
    vsh[threadIdx.x] = reinterpret_cast<const float4*>(g_v + (size_t)b * HH)[threadIdx.x];
    __syncthreads();

    const float4* ep = reinterpret_cast<const float4*>(enc) +
                       ((size_t)l0 * BB + b) * (HH / 4);
    const size_t row_stride = (size_t)BB * (HH / 4);

    float acc[LPW];
#pragma unroll
    for (int j = 0; j < LPW; ++j) acc[j] = 0.f;

    for (int j = 0; j < LPW; ++j) {
        const float4* row = ep + (size_t)j * row_stride;
        float4 x[8];
#pragma unroll
        for (int i = 0; i < 8; ++i)
            x[i] = __ldcs(row + i * 32 + lane);    // 8 LDG.128 in flight, evict-first
        float a0 = 0.f, a1 = 0.f, a2 = 0.f, a3 = 0.f;
#pragma unroll
        for (int i = 0; i < 8; ++i) {
            const float4 vv = vsh[i * 32 + lane];  // conflict-free LDS.128
            a0 = fmaf(x[i].x, vv.x, a0);
            a1 = fmaf(x[i].y, vv.y, a1);
            a2 = fmaf(x[i].z, vv.z, a2);
            a3 = fmaf(x[i].w, vv.w, a3);
        }
        acc[j] = (a0 + a1) + (a2 + a3);
    }

    // Deferred butterfly reductions: 16 independent chains overlap.
#pragma unroll
    for (int j = 0; j < LPW; ++j) {
#pragma unroll
        for (int o = 16; o; o >>= 1)
            acc[j] += __shfl_xor_sync(0xffffffffu, acc[j], o);
    }

    if (lane == 0) {
        float4* eo = reinterpret_cast<float4*>(g_energy + (size_t)b * LL + l0);
#pragma unroll
        for (int q = 0; q < LPW / 4; ++q)
            eo[q] = make_float4(acc[4 * q], acc[4 * q + 1], acc[4 * q + 2], acc[4 * q + 3]);
    }
}

// ---------------------------------------------------------------------------
// Kernel 4: row softmax over L=4096 per b; one block per b, 1024 threads,
// vectorized float4 I/O. Writes final output [B,1,L].
// ---------------------------------------------------------------------------
__global__ void softmax_kernel(float* __restrict__ out) {
    const int b = blockIdx.x;
    const int t = threadIdx.x;
    __shared__ float sh[32];
    __shared__ float bcast;

    float4 e = reinterpret_cast<const float4*>(g_energy + (size_t)b * LL)[t];

    float m = fmaxf(fmaxf(e.x, e.y), fmaxf(e.z, e.w));
#pragma unroll
    for (int o = 16; o; o >>= 1)
        m = fmaxf(m, __shfl_xor_sync(0xffffffffu, m, o));
    if ((t & 31) == 0) sh[t >> 5] = m;
    __syncthreads();
    if (t < 32) {
        float v = sh[t];
#pragma unroll
        for (int o = 16; o; o >>= 1)
            v = fmaxf(v, __shfl_xor_sync(0xffffffffu, v, o));
        if (t == 0) bcast = v;
    }
    __syncthreads();
    m = bcast;

    e.x = __expf(e.x - m); e.y = __expf(e.y - m);
    e.z = __expf(e.z - m); e.w = __expf(e.w - m);
    float s = (e.x + e.y) + (e.z + e.w);
#pragma unroll
    for (int o = 16; o; o >>= 1)
        s += __shfl_xor_sync(0xffffffffu, s, o);
    if ((t & 31) == 0) sh[t >> 5] = s;
    __syncthreads();
    if (t < 32) {
        float v = sh[t];
#pragma unroll
        for (int o = 16; o; o >>= 1)
            v += __shfl_xor_sync(0xffffffffu, v, o);
        if (t == 0) bcast = v;
    }
    __syncthreads();
    const float inv = 1.0f / bcast;
    e.x *= inv; e.y *= inv; e.z *= inv; e.w *= inv;
    reinterpret_cast<float4*>(out + (size_t)b * LL)[t] = e;
}

// ---------------------------------------------------------------------------
extern "C" void kernel_launch(void* const* d_in, const int* in_sizes, int n_in,
                              void* d_out, int out_size) {
    // Identify inputs by element count (all distinct): robust to ordering.
    const float* hid = nullptr;   // 32*1024      = 32768
    const float* enc = nullptr;   // 4096*32*1024 = 134217728
    const float* W   = nullptr;   // 1024*1024    = 1048576
    for (int i = 0; i < n_in; ++i) {
        const int s = in_sizes[i];
        if (s == BB * HH)            hid = (const float*)d_in[i];
        else if (s == HH * HH)       W   = (const float*)d_in[i];
        else if (s == 1024)          { /* bias: softmax-invariant (and zero) */ }
        else                         enc = (const float*)d_in[i];
    }
    float* out = (float*)d_out;

    gemv_partial_kernel<<<dim3(HH / 128, GCH), 128>>>(hid, W);
    fold_v_kernel<<<(BB * HH) / 256, 256>>>();
    energies_kernel<<<dim3(LL / (WPB * LPW), BB), 32 * WPB>>>(enc);
    softmax_kernel<<<BB, 1024>>>(out);
}

// round 7
// speedup vs baseline: 1.3844x; 1.0503x over previous
#include <cuda_runtime.h>
#include <cuda_bf16.h>
#include <cstdint>

// Problem constants (fixed by the reference)
#define BB 32
#define LL 4096
#define HH 1024
#define GCH 32           // g-dimension chunks for the hid@W gemv (32 g each)
#define LPW 32           // encoder rows handled per warp in energies (2 halves of 16)
#define WPB 8            // warps per block in energies
#define XCTAS (LL / (WPB * LPW))   // 16 x-CTAs per b

// Scratch (allocation-free rule: __device__ globals)
__device__ float g_vpart[GCH * BB * HH];   // 4 MiB
__device__ float g_v[BB * HH];             // 128 KB
__device__ float g_energy[BB * LL];        // 512 KB
__device__ int   g_cnt[BB];                // arrival counters (zeroed by fold kernel)

// ---------------------------------------------------------------------------
// Kernel 1: partial v[b,h] over a 32-wide g chunk, ALL 32 b batched per thread
// so W is read exactly once (4 MiB DRAM traffic total).
// grid (HH/128, GCH), 128 threads.
// ---------------------------------------------------------------------------
__global__ void gemv_partial_kernel(const float* __restrict__ hid,
                                    const float* __restrict__ W) {
    const int h  = blockIdx.x * 128 + threadIdx.x;
    const int g0 = blockIdx.y * (HH / GCH);   // 32-wide g chunk
    const int t  = threadIdx.x;

    // Stage hid[:, g0:g0+32]: 32 b x 32 g = 256 float4, two passes of 128 thr.
    __shared__ float hsh[BB][HH / GCH];
#pragma unroll
    for (int r = 0; r < 2; ++r) {
        const int b = r * 16 + (t >> 3);
        const int c = (t & 7) * 4;
        const float4 hv = *reinterpret_cast<const float4*>(hid + (size_t)b * HH + g0 + c);
        hsh[b][c + 0] = hv.x; hsh[b][c + 1] = hv.y;
        hsh[b][c + 2] = hv.z; hsh[b][c + 3] = hv.w;
    }
    __syncthreads();

    float acc[BB];
#pragma unroll
    for (int b = 0; b < BB; ++b) acc[b] = 0.f;

    const float* Wp = W + (size_t)g0 * HH + h;
#pragma unroll 8
    for (int g = 0; g < HH / GCH; ++g) {
        const float w = Wp[(size_t)g * HH];
#pragma unroll
        for (int b = 0; b < BB; ++b)
            acc[b] = fmaf(hsh[b][g], w, acc[b]);   // warp-uniform smem broadcast
    }

    float* vp = g_vpart + (size_t)blockIdx.y * BB * HH;
#pragma unroll
    for (int b = 0; b < BB; ++b)
        vp[(size_t)b * HH + h] = acc[b];
}

// ---------------------------------------------------------------------------
// Kernel 2: fold the GCH partials into g_v; also re-zero the arrival counters
// for the fused softmax (stream order guarantees this precedes energies).
// ---------------------------------------------------------------------------
__global__ void fold_v_kernel() {
    const int i = blockIdx.x * 256 + threadIdx.x;   // i < BB*HH
    if (blockIdx.x == 0 && threadIdx.x < BB) g_cnt[threadIdx.x] = 0;
    float s = 0.f;
#pragma unroll 8
    for (int c = 0; c < GCH; ++c) s += g_vpart[c * BB * HH + i];
    g_v[i] = s;
}

// ---------------------------------------------------------------------------
// Kernel 3: energies[b,l] = enc[l,b,:] . v[b,:]  + fused row softmax epilogue.
// grid (16, 32) = 512 CTAs -> ONE wave at 4 CTAs/SM (no wave quantization).
// Each warp: 32 rows, processed as 2 deferred-reduction batches of 16 (keeps
// live regs identical to the LPW=16 version). v[b] staged in 4 KB smem.
// The last-arriving CTA per b (fence + atomic counter) performs softmax over
// L=4096 with its 256 threads, reading g_energy from L2.
// ---------------------------------------------------------------------------
__global__ void __launch_bounds__(32 * WPB, 4)
energies_kernel(const float* __restrict__ enc, float* __restrict__ out) {
    const int warp = threadIdx.x >> 5;
    const int lane = threadIdx.x & 31;
    const int b    = blockIdx.y;
    const int l0   = (blockIdx.x * WPB + warp) * LPW;

    __shared__ float4 vsh[HH / 4];   // 4 KB: v[b] as 256 float4
    vsh[threadIdx.x] = reinterpret_cast<const float4*>(g_v + (size_t)b * HH)[threadIdx.x];
    __syncthreads();

    const float4* ep = reinterpret_cast<const float4*>(enc) +
                       ((size_t)l0 * BB + b) * (HH / 4);
    const size_t row_stride = (size_t)BB * (HH / 4);

#pragma unroll
    for (int half = 0; half < 2; ++half) {
        float acc[16];
#pragma unroll
        for (int j = 0; j < 16; ++j) acc[j] = 0.f;

        for (int j = 0; j < 16; ++j) {
            const float4* row = ep + (size_t)(half * 16 + j) * row_stride;
            float4 x[8];
#pragma unroll
            for (int i = 0; i < 8; ++i)
                x[i] = __ldcs(row + i * 32 + lane);    // 8 LDG.128 in flight
            float a0 = 0.f, a1 = 0.f, a2 = 0.f, a3 = 0.f;
#pragma unroll
            for (int i = 0; i < 8; ++i) {
                const float4 vv = vsh[i * 32 + lane];  // conflict-free LDS.128
                a0 = fmaf(x[i].x, vv.x, a0);
                a1 = fmaf(x[i].y, vv.y, a1);
                a2 = fmaf(x[i].z, vv.z, a2);
                a3 = fmaf(x[i].w, vv.w, a3);
            }
            acc[j] = (a0 + a1) + (a2 + a3);
        }

        // Deferred butterfly reductions: 16 independent chains overlap.
#pragma unroll
        for (int j = 0; j < 16; ++j) {
#pragma unroll
            for (int o = 16; o; o >>= 1)
                acc[j] += __shfl_xor_sync(0xffffffffu, acc[j], o);
        }
        if (lane == 0) {
            float4* eo = reinterpret_cast<float4*>(g_energy + (size_t)b * LL + l0 + half * 16);
#pragma unroll
            for (int q = 0; q < 4; ++q)
                eo[q] = make_float4(acc[4 * q], acc[4 * q + 1], acc[4 * q + 2], acc[4 * q + 3]);
        }
    }

    // ---- arrival: is this the last CTA for row b? ----
    __threadfence();
    __syncthreads();
    __shared__ int s_last;
    if (threadIdx.x == 0)
        s_last = (atomicAdd(&g_cnt[b], 1) == XCTAS - 1);
    __syncthreads();
    if (!s_last) return;

    // ---- fused softmax over L=4096 for row b (256 threads, 16 vals each) ----
    const int t = threadIdx.x;
    __shared__ float sh[WPB];
    __shared__ float bcast;
    const float4* ebase = reinterpret_cast<const float4*>(g_energy + (size_t)b * LL);

    float4 e[4];
    float m = -1e30f;
#pragma unroll
    for (int k = 0; k < 4; ++k) {
        e[k] = ebase[t + k * 256];
        m = fmaxf(m, fmaxf(fmaxf(e[k].x, e[k].y), fmaxf(e[k].z, e[k].w)));
    }
#pragma unroll
    for (int o = 16; o; o >>= 1)
        m = fmaxf(m, __shfl_xor_sync(0xffffffffu, m, o));
    if (lane == 0) sh[warp] = m;
    __syncthreads();
    if (t < 32) {
        float v = sh[t & (WPB - 1)];
#pragma unroll
        for (int o = WPB / 2; o; o >>= 1)
            v = fmaxf(v, __shfl_xor_sync(0xffffffffu, v, o));
        if (t == 0) bcast = v;
    }
    __syncthreads();
    m = bcast;

    float s = 0.f;
#pragma unroll
    for (int k = 0; k < 4; ++k) {
        e[k].x = __expf(e[k].x - m); e[k].y = __expf(e[k].y - m);
        e[k].z = __expf(e[k].z - m); e[k].w = __expf(e[k].w - m);
        s += (e[k].x + e[k].y) + (e[k].z + e[k].w);
    }
#pragma unroll
    for (int o = 16; o; o >>= 1)
        s += __shfl_xor_sync(0xffffffffu, s, o);
    if (lane == 0) sh[warp] = s;
    __syncthreads();
    if (t < 32) {
        float v = sh[t & (WPB - 1)];
#pragma unroll
        for (int o = WPB / 2; o; o >>= 1)
            v += __shfl_xor_sync(0xffffffffu, v, o);
        if (t == 0) bcast = v;
    }
    __syncthreads();
    const float inv = 1.0f / bcast;

    float4* op = reinterpret_cast<float4*>(out + (size_t)b * LL);
#pragma unroll
    for (int k = 0; k < 4; ++k) {
        e[k].x *= inv; e[k].y *= inv; e[k].z *= inv; e[k].w *= inv;
        op[t + k * 256] = e[k];
    }
}

// ---------------------------------------------------------------------------
extern "C" void kernel_launch(void* const* d_in, const int* in_sizes, int n_in,
                              void* d_out, int out_size) {
    // Identify inputs by element count (all distinct): robust to ordering.
    const float* hid = nullptr;   // 32*1024      = 32768
    const float* enc = nullptr;   // 4096*32*1024 = 134217728
    const float* W   = nullptr;   // 1024*1024    = 1048576
    for (int i = 0; i < n_in; ++i) {
        const int s = in_sizes[i];
        if (s == BB * HH)            hid = (const float*)d_in[i];
        else if (s == HH * HH)       W   = (const float*)d_in[i];
        else if (s == 1024)          { /* bias: softmax-invariant (and zero) */ }
        else                         enc = (const float*)d_in[i];
    }
    float* out = (float*)d_out;

    gemv_partial_kernel<<<dim3(HH / 128, GCH), 128>>>(hid, W);
    fold_v_kernel<<<(BB * HH) / 256, 256>>>();
    energies_kernel<<<dim3(XCTAS, BB), 32 * WPB>>>(enc, out);
}

// round 8
// speedup vs baseline: 1.4018x; 1.0126x over previous
#include <cuda_runtime.h>
#include <cuda_bf16.h>
#include <cstdint>

// Problem constants (fixed by the reference)
#define BB 32
#define LL 4096
#define HH 1024
#define GCH 32           // g-dimension chunks for the hid@W gemv (32 g each)
#define BCH 8            // b per thread in gemv (BB/BCH = 4 b-groups)
#define LPW 32           // encoder rows handled per warp in energies (2 halves of 16)
#define WPB 8            // warps per block in energies
#define XCTAS (LL / (WPB * LPW))   // 16 x-CTAs per b

// Scratch (allocation-free rule: __device__ globals)
__device__ float g_vpart[GCH * BB * HH];   // 4 MiB
__device__ float g_v[BB * HH];             // 128 KB
__device__ float g_energy[BB * LL];        // 512 KB
__device__ int   g_cnt[BB];                // arrival counters (zeroed by fold kernel)

// ---------------------------------------------------------------------------
// Kernel 1: partial v[b,h] over a 32-wide g chunk and an 8-wide b group.
// grid (HH/128, GCH, BB/BCH) = 1024 CTAs (~7/SM) -- R7 fix: the old 256-CTA
// shape was latency-starved (occ 10%, 10.75us). Each thread: 1 h, 32 g (fully
// unrolled -> 32 independent LDGs in flight), 8 b accumulators (~30 regs).
// ---------------------------------------------------------------------------
__global__ void gemv_partial_kernel(const float* __restrict__ hid,
                                    const float* __restrict__ W) {
    const int h  = blockIdx.x * 128 + threadIdx.x;
    const int g0 = blockIdx.y * (HH / GCH);   // 32-wide g chunk
    const int b0 = blockIdx.z * BCH;          // 8-wide b group

    // Stage hid[b0:b0+8, g0:g0+32]: 256 floats = 64 float4 (threads 0..63)
    __shared__ float hsh[BCH][HH / GCH];
    if (threadIdx.x < 64) {
        const int b = threadIdx.x >> 3;
        const int c = (threadIdx.x & 7) * 4;
        const float4 hv = *reinterpret_cast<const float4*>(
            hid + (size_t)(b0 + b) * HH + g0 + c);
        hsh[b][c + 0] = hv.x; hsh[b][c + 1] = hv.y;
        hsh[b][c + 2] = hv.z; hsh[b][c + 3] = hv.w;
    }
    __syncthreads();

    float acc[BCH];
#pragma unroll
    for (int b = 0; b < BCH; ++b) acc[b] = 0.f;

    const float* Wp = W + (size_t)g0 * HH + h;
#pragma unroll
    for (int g = 0; g < HH / GCH; ++g) {
        const float w = Wp[(size_t)g * HH];    // coalesced; 32 loads batched
#pragma unroll
        for (int b = 0; b < BCH; ++b)
            acc[b] = fmaf(hsh[b][g], w, acc[b]);   // warp-uniform smem broadcast
    }

    float* vp = g_vpart + (size_t)blockIdx.y * BB * HH;
#pragma unroll
    for (int b = 0; b < BCH; ++b)
        vp[(size_t)(b0 + b) * HH + h] = acc[b];
}

// ---------------------------------------------------------------------------
// Kernel 2: fold the GCH partials into g_v; also re-zero the arrival counters
// for the fused softmax (stream order guarantees this precedes energies).
// ---------------------------------------------------------------------------
__global__ void fold_v_kernel() {
    const int i = blockIdx.x * 256 + threadIdx.x;   // i < BB*HH
    if (blockIdx.x == 0 && threadIdx.x < BB) g_cnt[threadIdx.x] = 0;
    float s = 0.f;
#pragma unroll 8
    for (int c = 0; c < GCH; ++c) s += g_vpart[c * BB * HH + i];
    g_v[i] = s;
}

// ---------------------------------------------------------------------------
// Kernel 3: energies[b,l] = enc[l,b,:] . v[b,:]  + fused row softmax epilogue.
// grid (16, 32) = 512 CTAs -> ONE wave at 4 CTAs/SM (no wave quantization).
// Each warp: 32 rows as 2 deferred-reduction batches of 16. v[b] in 4 KB smem.
// Last-arriving CTA per b (fence + atomic counter) does the 4096-wide softmax.
// ---------------------------------------------------------------------------
__global__ void __launch_bounds__(32 * WPB, 4)
energies_kernel(const float* __restrict__ enc, float* __restrict__ out) {
    const int warp = threadIdx.x >> 5;
    const int lane = threadIdx.x & 31;
    const int b    = blockIdx.y;
    const int l0   = (blockIdx.x * WPB + warp) * LPW;

    __shared__ float4 vsh[HH / 4];   // 4 KB: v[b] as 256 float4
    vsh[threadIdx.x] = reinterpret_cast<const float4*>(g_v + (size_t)b * HH)[threadIdx.x];
    __syncthreads();

    const float4* ep = reinterpret_cast<const float4*>(enc) +
                       ((size_t)l0 * BB + b) * (HH / 4);
    const size_t row_stride = (size_t)BB * (HH / 4);

#pragma unroll
    for (int half = 0; half < 2; ++half) {
        float acc[16];
#pragma unroll
        for (int j = 0; j < 16; ++j) acc[j] = 0.f;

        for (int j = 0; j < 16; ++j) {
            const float4* row = ep + (size_t)(half * 16 + j) * row_stride;
            float4 x[8];
#pragma unroll
            for (int i = 0; i < 8; ++i)
                x[i] = __ldcs(row + i * 32 + lane);    // 8 LDG.128 in flight
            float a0 = 0.f, a1 = 0.f, a2 = 0.f, a3 = 0.f;
#pragma unroll
            for (int i = 0; i < 8; ++i) {
                const float4 vv = vsh[i * 32 + lane];  // conflict-free LDS.128
                a0 = fmaf(x[i].x, vv.x, a0);
                a1 = fmaf(x[i].y, vv.y, a1);
                a2 = fmaf(x[i].z, vv.z, a2);
                a3 = fmaf(x[i].w, vv.w, a3);
            }
            acc[j] = (a0 + a1) + (a2 + a3);
        }

        // Deferred butterfly reductions: 16 independent chains overlap.
#pragma unroll
        for (int j = 0; j < 16; ++j) {
#pragma unroll
            for (int o = 16; o; o >>= 1)
                acc[j] += __shfl_xor_sync(0xffffffffu, acc[j], o);
        }
        if (lane == 0) {
            float4* eo = reinterpret_cast<float4*>(g_energy + (size_t)b * LL + l0 + half * 16);
#pragma unroll
            for (int q = 0; q < 4; ++q)
                eo[q] = make_float4(acc[4 * q], acc[4 * q + 1], acc[4 * q + 2], acc[4 * q + 3]);
        }
    }

    // ---- arrival: is this the last CTA for row b? ----
    __threadfence();
    __syncthreads();
    __shared__ int s_last;
    if (threadIdx.x == 0)
        s_last = (atomicAdd(&g_cnt[b], 1) == XCTAS - 1);
    __syncthreads();
    if (!s_last) return;

    // ---- fused softmax over L=4096 for row b (256 threads, 16 vals each) ----
    const int t = threadIdx.x;
    __shared__ float sh[WPB];
    __shared__ float bcast;
    const float4* ebase = reinterpret_cast<const float4*>(g_energy + (size_t)b * LL);

    float4 e[4];
    float m = -1e30f;
#pragma unroll
    for (int k = 0; k < 4; ++k) {
        e[k] = ebase[t + k * 256];
        m = fmaxf(m, fmaxf(fmaxf(e[k].x, e[k].y), fmaxf(e[k].z, e[k].w)));
    }
#pragma unroll
    for (int o = 16; o; o >>= 1)
        m = fmaxf(m, __shfl_xor_sync(0xffffffffu, m, o));
    if (lane == 0) sh[warp] = m;
    __syncthreads();
    if (t < 32) {
        float v = sh[t & (WPB - 1)];
#pragma unroll
        for (int o = WPB / 2; o; o >>= 1)
            v = fmaxf(v, __shfl_xor_sync(0xffffffffu, v, o));
        if (t == 0) bcast = v;
    }
    __syncthreads();
    m = bcast;

    float s = 0.f;
#pragma unroll
    for (int k = 0; k < 4; ++k) {
        e[k].x = __expf(e[k].x - m); e[k].y = __expf(e[k].y - m);
        e[k].z = __expf(e[k].z - m); e[k].w = __expf(e[k].w - m);
        s += (e[k].x + e[k].y) + (e[k].z + e[k].w);
    }
#pragma unroll
    for (int o = 16; o; o >>= 1)
        s += __shfl_xor_sync(0xffffffffu, s, o);
    if (lane == 0) sh[warp] = s;
    __syncthreads();
    if (t < 32) {
        float v = sh[t & (WPB - 1)];
#pragma unroll
        for (int o = WPB / 2; o; o >>= 1)
            v += __shfl_xor_sync(0xffffffffu, v, o);
        if (t == 0) bcast = v;
    }
    __syncthreads();
    const float inv = 1.0f / bcast;

    float4* op = reinterpret_cast<float4*>(out + (size_t)b * LL);
#pragma unroll
    for (int k = 0; k < 4; ++k) {
        e[k].x *= inv; e[k].y *= inv; e[k].z *= inv; e[k].w *= inv;
        op[t + k * 256] = e[k];
    }
}

// ---------------------------------------------------------------------------
extern "C" void kernel_launch(void* const* d_in, const int* in_sizes, int n_in,
                              void* d_out, int out_size) {
    // Identify inputs by element count (all distinct): robust to ordering.
    const float* hid = nullptr;   // 32*1024      = 32768
    const float* enc = nullptr;   // 4096*32*1024 = 134217728
    const float* W   = nullptr;   // 1024*1024    = 1048576
    for (int i = 0; i < n_in; ++i) {
        const int s = in_sizes[i];
        if (s == BB * HH)            hid = (const float*)d_in[i];
        else if (s == HH * HH)       W   = (const float*)d_in[i];
        else if (s == 1024)          { /* bias: softmax-invariant (and zero) */ }
        else                         enc = (const float*)d_in[i];
    }
    float* out = (float*)d_out;

    gemv_partial_kernel<<<dim3(HH / 128, GCH, BB / BCH), 128>>>(hid, W);
    fold_v_kernel<<<(BB * HH) / 256, 256>>>();
    energies_kernel<<<dim3(XCTAS, BB), 32 * WPB>>>(enc, out);
}